// round 3
// baseline (speedup 1.0000x reference)
#include <cuda_runtime.h>
#include <math.h>

#define NN 50000
#define EE 800000
#define INC 128
#define HID 64
#define NHEADS 4
#define HCMAX 256
#define NGR 64
#define NCLS 10
#define EPSV 1e-5f
#define SLOPE 0.2f

// ---------------- scratch (device globals; no allocation allowed) ----------------
__device__ float g_H[(size_t)NN * HCMAX];   // GEMM output (h)
__device__ float g_O[(size_t)NN * HCMAX];   // aggregated output
__device__ float g_AS[NN * NHEADS];
__device__ float g_AD[NN * NHEADS];
__device__ float g_DEN[NN * NHEADS];
__device__ float g_EX[(size_t)EE * NHEADS];
__device__ float g_SUM[HCMAX];
__device__ float g_SQ[HCMAX];
__device__ float g_SC[HCMAX];
__device__ float g_SH[HCMAX];
__device__ float g_PL[NGR * HID];
__device__ float g_CT[NGR];

__device__ __forceinline__ void red_add4(float* p, float a, float b, float c, float d) {
    asm volatile("red.global.add.v4.f32 [%0], {%1,%2,%3,%4};"
                 :: "l"(p), "f"(a), "f"(b), "f"(c), "f"(d) : "memory");
}

// ---------------- SGEMM: C[M,N] = A[M,K] @ B[K,N], 128x64 tile, 8x4/thread ----------------
// 256 threads: ty in [0,16) covers 16*8=128 rows, tx in [0,16) covers 16*4=64 cols.
// Per k-step per thread: 32 FMA, 3 LDS.128 -> FMA-limited.
__global__ __launch_bounds__(256) void sgemm128x64(
        const float* __restrict__ A, const float* __restrict__ B,
        float* __restrict__ C, int M, int N, int K) {
    __shared__ float As[16][128];   // [k][row]
    __shared__ float Bs[16][64];    // [k][col]
    int tid = threadIdx.x;
    int tx = tid & 15, ty = tid >> 4;
    int row0 = blockIdx.y << 7, col0 = blockIdx.x << 6;

    // A tile load mapping: 512 float4 (128 rows x 4 quads); thread does f=tid, f=tid+256
    int ar0 = tid >> 2, aq0 = (tid & 3) << 2;          // first float4: row, k-quad
    int ar1 = (tid + 256) >> 2, aq1 = aq0;             // second float4 (rows 64..127)
    // B tile load: 256 float4 (16 rows x 16 quads)
    int br = tid >> 4, bc = (tid & 15) << 2;

    bool av0 = (row0 + ar0) < M;
    bool av1 = (row0 + ar1) < M;
    const float* Ap0 = A + (size_t)(row0 + ar0) * K + aq0;
    const float* Ap1 = A + (size_t)(row0 + ar1) * K + aq1;
    const float* Bp = B + (size_t)br * N + col0 + bc;

    float acc[8][4] = {};
    for (int kk = 0; kk < K; kk += 16) {
        float4 a0 = av0 ? *(const float4*)(Ap0 + kk) : make_float4(0.f, 0.f, 0.f, 0.f);
        float4 a1 = av1 ? *(const float4*)(Ap1 + kk) : make_float4(0.f, 0.f, 0.f, 0.f);
        As[aq0 + 0][ar0] = a0.x; As[aq0 + 1][ar0] = a0.y;
        As[aq0 + 2][ar0] = a0.z; As[aq0 + 3][ar0] = a0.w;
        As[aq1 + 0][ar1] = a1.x; As[aq1 + 1][ar1] = a1.y;
        As[aq1 + 2][ar1] = a1.z; As[aq1 + 3][ar1] = a1.w;
        *(float4*)&Bs[br][bc] = *(const float4*)(Bp + (size_t)kk * N);
        __syncthreads();
#pragma unroll
        for (int k = 0; k < 16; k++) {
            float4 aA = *(float4*)&As[k][(ty << 3) + 0];
            float4 aB = *(float4*)&As[k][(ty << 3) + 4];
            float4 b  = *(float4*)&Bs[k][tx << 2];
            float av[8] = {aA.x, aA.y, aA.z, aA.w, aB.x, aB.y, aB.z, aB.w};
#pragma unroll
            for (int i = 0; i < 8; i++) {
                acc[i][0] += av[i] * b.x;
                acc[i][1] += av[i] * b.y;
                acc[i][2] += av[i] * b.z;
                acc[i][3] += av[i] * b.w;
            }
        }
        __syncthreads();
    }
#pragma unroll
    for (int i = 0; i < 8; i++) {
        int row = row0 + (ty << 3) + i;
        if (row < M)
            *(float4*)&C[(size_t)row * N + col0 + (tx << 2)] =
                make_float4(acc[i][0], acc[i][1], acc[i][2], acc[i][3]);
    }
}

// ---------------- per-node attention logits: AS/AD[n,h] = dot(h[n,h,:], a_{src,dst}[h,:]) ----------
__global__ void attn_logits(const float* __restrict__ H, const float* __restrict__ a_src,
                            const float* __restrict__ a_dst, float* __restrict__ AS,
                            float* __restrict__ AD, int Hn) {
    int w = (blockIdx.x * blockDim.x + threadIdx.x) >> 5;
    int lane = threadIdx.x & 31;
    if (w >= NN * Hn) return;
    int n = w / Hn, h = w - n * Hn;
    const float* hp = H + (size_t)n * Hn * HID + h * HID;
    const float* sp = a_src + h * HID;
    const float* dp = a_dst + h * HID;
    float v1 = hp[lane], v2 = hp[lane + 32];
    float s = v1 * sp[lane] + v2 * sp[lane + 32];
    float d = v1 * dp[lane] + v2 * dp[lane + 32];
#pragma unroll
    for (int o = 16; o; o >>= 1) {
        s += __shfl_down_sync(0xffffffffu, s, o);
        d += __shfl_down_sync(0xffffffffu, d, o);
    }
    if (lane == 0) { AS[w] = s; AD[w] = d; }
}

// ---------------- edge pass 1: ex = exp(leaky(as[src]+ad[dst])), denom += ex ----------------
__global__ void edge_ex(const int* __restrict__ src, const int* __restrict__ dst,
                        const float* __restrict__ AS, const float* __restrict__ AD,
                        float* __restrict__ EX, float* __restrict__ DEN, int Hn) {
    int stride = gridDim.x * blockDim.x;
    for (int idx = blockIdx.x * blockDim.x + threadIdx.x; idx < EE * Hn; idx += stride) {
        int e = idx / Hn, h = idx - e * Hn;
        int s = __ldg(&src[e]), d = __ldg(&dst[e]);
        float v = __ldg(&AS[s * Hn + h]) + __ldg(&AD[d * Hn + h]);
        v = v > 0.f ? v : SLOPE * v;
        float ex = __expf(v);
        EX[idx] = ex;
        atomicAdd(&DEN[d * Hn + h], ex);
    }
}

// ---------------- edge pass 2: OUT[dst] += alpha * h[src] (vector red) ----------------
// 64 lanes per edge when HCl=256 (16 when HCl=64); each lane handles one float4.
__global__ void edge_agg(const float* __restrict__ H, const float* __restrict__ EX,
                         const float* __restrict__ DEN, const int* __restrict__ src,
                         const int* __restrict__ dst, float* __restrict__ OUT, int Hn) {
    int HCl = Hn * HID;
    int lanes = HCl >> 2;            // 64 or 16
    long long idx = (long long)blockIdx.x * blockDim.x + threadIdx.x;
    if (idx >= (long long)EE * lanes) return;
    int e = (int)(idx / lanes);
    int l = (int)(idx - (long long)e * lanes);
    int c4 = l << 2;
    int h = c4 >> 6;                 // 16 lanes share one head
    int s = __ldg(&src[e]), d = __ldg(&dst[e]);
    // alpha computed once per 16-lane head-slice, broadcast within the warp.
    float alpha = 0.f;
    int lane = threadIdx.x & 31;
    if ((l & 15) == 0) alpha = __ldg(&EX[(size_t)e * Hn + h]) / __ldg(&DEN[d * Hn + h]);
    alpha = __shfl_sync(0xffffffffu, alpha, lane & ~15);
    float4 v = *(const float4*)&H[(size_t)s * HCl + c4];
    red_add4(&OUT[(size_t)d * HCl + c4], v.x * alpha, v.y * alpha, v.z * alpha, v.w * alpha);
}

// ---------------- relu(x+b) in place + BN partial stats ----------------
__global__ void relu_bias_stats(float* __restrict__ X, const float* __restrict__ b,
                                float* __restrict__ sum, float* __restrict__ sq, int C) {
    int c = threadIdx.x;  // blockDim.x == C
    float bb = b[c];
    float s = 0.f, s2 = 0.f;
    for (int r = blockIdx.x; r < NN; r += gridDim.x) {
        float v = X[(size_t)r * C + c] + bb;
        v = fmaxf(v, 0.f);
        X[(size_t)r * C + c] = v;
        s += v; s2 += v * v;
    }
    atomicAdd(&sum[c], s);
    atomicAdd(&sq[c], s2);
}

__global__ void bn_finalize(const float* __restrict__ sum, const float* __restrict__ sq,
                            const float* __restrict__ g, const float* __restrict__ be,
                            float* __restrict__ sc, float* __restrict__ sh) {
    int c = threadIdx.x;
    float m = sum[c] / (float)NN;
    float var = sq[c] / (float)NN - m * m;
    float s = rsqrtf(var + EPSV) * g[c];
    sc[c] = s;
    sh[c] = be[c] - m * s;
}

__global__ void bn_apply(float* __restrict__ X, const float* __restrict__ sc,
                         const float* __restrict__ sh, int C, int total) {
    int i = blockIdx.x * blockDim.x + threadIdx.x;
    if (i >= total) return;
    int c = i % C;
    X[i] = X[i] * sc[c] + sh[c];
}

// ---------------- global mean pool ----------------
__global__ void pool_kernel(const float* __restrict__ H, const int* __restrict__ batch,
                            float* __restrict__ pool, float* __restrict__ cnt) {
    int idx = blockIdx.x * blockDim.x + threadIdx.x;
    if (idx >= NN * 16) return;
    int n = idx >> 4, l = idx & 15;
    int g = __ldg(&batch[n]);
    float4 v = *(const float4*)&H[(size_t)n * HID + (l << 2)];
    red_add4(&pool[g * HID + (l << 2)], v.x, v.y, v.z, v.w);
    if (l == 0) atomicAdd(&cnt[g], 1.0f);
}

__global__ void final_fc(const float* __restrict__ pool, const float* __restrict__ cnt,
                         const float* __restrict__ fcW, const float* __restrict__ fcb,
                         float* __restrict__ out) {
    int tid = threadIdx.x;
    if (tid >= NGR * NCLS) return;
    int g = tid / NCLS, k = tid - g * NCLS;
    float s = 0.f;
#pragma unroll
    for (int c = 0; c < HID; c++) s += pool[g * HID + c] * fcW[c * NCLS + k];
    float cc = fmaxf(cnt[g], 1.0f);
    out[tid] = s / cc + fcb[k];
}

// ---------------- host orchestration ----------------
static inline int cdiv(long long a, int b) { return (int)((a + b - 1) / b); }

struct Scratch {
    float *H, *O, *AS, *AD, *DEN, *EX, *SUM, *SQ, *SC, *SH, *PL, *CT;
};

static void run_layer(const float* X, int K, int Hn, const float* W,
                      const float* asv, const float* adv, const float* b,
                      const float* g, const float* be,
                      const int* src, const int* dst, const Scratch& S) {
    int HCl = Hn * HID;
    dim3 grid(HCl / 64, cdiv(NN, 128));
    sgemm128x64<<<grid, 256>>>(X, W, S.H, NN, HCl, K);

    int nw = NN * Hn;
    attn_logits<<<cdiv((long long)nw * 32, 256), 256>>>(S.H, asv, adv, S.AS, S.AD, Hn);

    cudaMemsetAsync(S.DEN, 0, (size_t)NN * Hn * sizeof(float));
    cudaMemsetAsync(S.O, 0, (size_t)NN * HCl * sizeof(float));

    edge_ex<<<1184, 256>>>(src, dst, S.AS, S.AD, S.EX, S.DEN, Hn);
    edge_agg<<<cdiv((long long)EE * (HCl / 4), 256), 256>>>(S.H, S.EX, S.DEN, src, dst, S.O, Hn);

    cudaMemsetAsync(S.SUM, 0, HCl * sizeof(float));
    cudaMemsetAsync(S.SQ, 0, HCl * sizeof(float));
    relu_bias_stats<<<512, HCl>>>(S.O, b, S.SUM, S.SQ, HCl);
    bn_finalize<<<1, HCl>>>(S.SUM, S.SQ, g, be, S.SC, S.SH);
    bn_apply<<<cdiv((long long)NN * HCl, 256), 256>>>(S.O, S.SC, S.SH, HCl, NN * HCl);
}

extern "C" void kernel_launch(void* const* d_in, const int* in_sizes, int n_in,
                              void* d_out, int out_size) {
    const float* x      = (const float*)d_in[0];
    const int*   ei     = (const int*)d_in[1];
    const int*   batch  = (const int*)d_in[2];
    const float* W1     = (const float*)d_in[3];
    const float* a_src1 = (const float*)d_in[4];
    const float* a_dst1 = (const float*)d_in[5];
    const float* b1     = (const float*)d_in[6];
    const float* g1     = (const float*)d_in[7];
    const float* be1    = (const float*)d_in[8];
    const float* W2     = (const float*)d_in[9];
    const float* a_src2 = (const float*)d_in[10];
    const float* a_dst2 = (const float*)d_in[11];
    const float* b2     = (const float*)d_in[12];
    const float* g2     = (const float*)d_in[13];
    const float* be2    = (const float*)d_in[14];
    const float* W3     = (const float*)d_in[15];
    const float* a_src3 = (const float*)d_in[16];
    const float* a_dst3 = (const float*)d_in[17];
    const float* b3     = (const float*)d_in[18];
    const float* g3     = (const float*)d_in[19];
    const float* be3    = (const float*)d_in[20];
    const float* fcW    = (const float*)d_in[21];
    const float* fcb    = (const float*)d_in[22];
    const int* src = ei;
    const int* dst = ei + EE;

    Scratch S;
    cudaGetSymbolAddress((void**)&S.H,  g_H);
    cudaGetSymbolAddress((void**)&S.O,  g_O);
    cudaGetSymbolAddress((void**)&S.AS, g_AS);
    cudaGetSymbolAddress((void**)&S.AD, g_AD);
    cudaGetSymbolAddress((void**)&S.DEN, g_DEN);
    cudaGetSymbolAddress((void**)&S.EX, g_EX);
    cudaGetSymbolAddress((void**)&S.SUM, g_SUM);
    cudaGetSymbolAddress((void**)&S.SQ, g_SQ);
    cudaGetSymbolAddress((void**)&S.SC, g_SC);
    cudaGetSymbolAddress((void**)&S.SH, g_SH);
    cudaGetSymbolAddress((void**)&S.PL, g_PL);
    cudaGetSymbolAddress((void**)&S.CT, g_CT);

    // Layer 1: in=128 -> 4x64 concat (256)
    run_layer(x,   INC,   NHEADS, W1, a_src1, a_dst1, b1, g1, be1, src, dst, S);
    // Layer 2: 256 -> 4x64 concat (256)
    run_layer(S.O, HCMAX, NHEADS, W2, a_src2, a_dst2, b2, g2, be2, src, dst, S);
    // Layer 3: 256 -> 1x64 (mean over 1 head == identity)
    run_layer(S.O, HCMAX, 1,      W3, a_src3, a_dst3, b3, g3, be3, src, dst, S);

    // Global mean pool + classifier
    cudaMemsetAsync(S.PL, 0, NGR * HID * sizeof(float));
    cudaMemsetAsync(S.CT, 0, NGR * sizeof(float));
    pool_kernel<<<cdiv((long long)NN * 16, 256), 256>>>(S.O, batch, S.PL, S.CT);
    final_fc<<<1, NGR * NCLS>>>(S.PL, S.CT, fcW, fcb, (float*)d_out);
}

// round 15
// speedup vs baseline: 1.6013x; 1.6013x over previous
#include <cuda_runtime.h>
#include <math.h>

#define NN 50000
#define EE 800000
#define INC 128
#define HID 64
#define NHEADS 4
#define HCMAX 256
#define NGR 64
#define NCLS 10
#define EPSV 1e-5f
#define SLOPE 0.2f

// ---------------- scratch (device globals; no allocation allowed) ----------------
__device__ float g_H[(size_t)NN * HCMAX];   // GEMM output (h)
__device__ float g_O[(size_t)NN * HCMAX];   // aggregated output
__device__ float g_AS[NN * NHEADS];
__device__ float g_AD[NN * NHEADS];
__device__ float g_DEN[NN * NHEADS];
__device__ float g_SUM[HCMAX];
__device__ float g_SQ[HCMAX];
__device__ float g_SC[HCMAX];
__device__ float g_SH[HCMAX];
__device__ float g_PL[NGR * HID];
__device__ float g_CT[NGR];

__device__ __forceinline__ void red_add4(float* p, float a, float b, float c, float d) {
    asm volatile("red.global.add.v4.f32 [%0], {%1,%2,%3,%4};"
                 :: "l"(p), "f"(a), "f"(b), "f"(c), "f"(d) : "memory");
}

__device__ __forceinline__ void red_add1(float* p, float a) {
    asm volatile("red.global.add.f32 [%0], %1;" :: "l"(p), "f"(a) : "memory");
}

__device__ __forceinline__ float leaky(float v) { return v > 0.f ? v : SLOPE * v; }

// ---------------- SGEMM: C[M,N] = (affine(A))[M,K] @ B[K,N], 128x64 tile, 8x4/thread ------
// Optional per-K-channel affine on A (folds previous layer's BN): a = a*sc[k]+sh[k].
__global__ __launch_bounds__(256) void sgemm128x64(
        const float* __restrict__ A, const float* __restrict__ B,
        float* __restrict__ C, int M, int N, int K,
        const float* __restrict__ sc, const float* __restrict__ sh) {
    __shared__ float As[16][128];   // [k][row]
    __shared__ float Bs[16][64];    // [k][col]
    int tid = threadIdx.x;
    int tx = tid & 15, ty = tid >> 4;
    int row0 = blockIdx.y << 7, col0 = blockIdx.x << 6;

    int ar0 = tid >> 2, aq0 = (tid & 3) << 2;          // A float4 #1: row, k-quad
    int ar1 = (tid + 256) >> 2;                         // A float4 #2 (rows 64..127)
    int br = tid >> 4, bc = (tid & 15) << 2;            // B tile: 16 k x 64 cols

    bool av0 = (row0 + ar0) < M;
    bool av1 = (row0 + ar1) < M;
    const float* Ap0 = A + (size_t)(row0 + ar0) * K + aq0;
    const float* Ap1 = A + (size_t)(row0 + ar1) * K + aq0;
    const float* Bp = B + (size_t)br * N + col0 + bc;
    bool affine = (sc != nullptr);

    float acc[8][4] = {};
    for (int kk = 0; kk < K; kk += 16) {
        float4 a0 = av0 ? *(const float4*)(Ap0 + kk) : make_float4(0.f, 0.f, 0.f, 0.f);
        float4 a1 = av1 ? *(const float4*)(Ap1 + kk) : make_float4(0.f, 0.f, 0.f, 0.f);
        if (affine) {
            float4 s4 = *(const float4*)&sc[kk + aq0];
            float4 h4 = *(const float4*)&sh[kk + aq0];
            a0.x = a0.x * s4.x + h4.x; a0.y = a0.y * s4.y + h4.y;
            a0.z = a0.z * s4.z + h4.z; a0.w = a0.w * s4.w + h4.w;
            a1.x = a1.x * s4.x + h4.x; a1.y = a1.y * s4.y + h4.y;
            a1.z = a1.z * s4.z + h4.z; a1.w = a1.w * s4.w + h4.w;
        }
        As[aq0 + 0][ar0] = a0.x; As[aq0 + 1][ar0] = a0.y;
        As[aq0 + 2][ar0] = a0.z; As[aq0 + 3][ar0] = a0.w;
        As[aq0 + 0][ar1] = a1.x; As[aq0 + 1][ar1] = a1.y;
        As[aq0 + 2][ar1] = a1.z; As[aq0 + 3][ar1] = a1.w;
        *(float4*)&Bs[br][bc] = *(const float4*)(Bp + (size_t)kk * N);
        __syncthreads();
#pragma unroll
        for (int k = 0; k < 16; k++) {
            float4 aA = *(float4*)&As[k][(ty << 3) + 0];
            float4 aB = *(float4*)&As[k][(ty << 3) + 4];
            float4 b  = *(float4*)&Bs[k][tx << 2];
            float av[8] = {aA.x, aA.y, aA.z, aA.w, aB.x, aB.y, aB.z, aB.w};
#pragma unroll
            for (int i = 0; i < 8; i++) {
                acc[i][0] += av[i] * b.x;
                acc[i][1] += av[i] * b.y;
                acc[i][2] += av[i] * b.z;
                acc[i][3] += av[i] * b.w;
            }
        }
        __syncthreads();
    }
#pragma unroll
    for (int i = 0; i < 8; i++) {
        int row = row0 + (ty << 3) + i;
        if (row < M)
            *(float4*)&C[(size_t)row * N + col0 + (tx << 2)] =
                make_float4(acc[i][0], acc[i][1], acc[i][2], acc[i][3]);
    }
}

// ---------------- per-node attention logits: AS/AD[n,h] = dot(h[n,h,:], a_{src,dst}[h,:]) ----------
__global__ void attn_logits(const float* __restrict__ H, const float* __restrict__ a_src,
                            const float* __restrict__ a_dst, float* __restrict__ AS,
                            float* __restrict__ AD, int Hn) {
    int w = (blockIdx.x * blockDim.x + threadIdx.x) >> 5;
    int lane = threadIdx.x & 31;
    if (w >= NN * Hn) return;
    int n = w / Hn, h = w - n * Hn;
    const float* hp = H + (size_t)n * Hn * HID + h * HID;
    const float* sp = a_src + h * HID;
    const float* dp = a_dst + h * HID;
    float v1 = hp[lane], v2 = hp[lane + 32];
    float s = v1 * sp[lane] + v2 * sp[lane + 32];
    float d = v1 * dp[lane] + v2 * dp[lane + 32];
#pragma unroll
    for (int o = 16; o; o >>= 1) {
        s += __shfl_down_sync(0xffffffffu, s, o);
        d += __shfl_down_sync(0xffffffffu, d, o);
    }
    if (lane == 0) { AS[w] = s; AD[w] = d; }
}

// ---------------- edge pass 1 (Hn=4): denom[dst,:] += exp(leaky(AS4[src]+AD4[dst])) ------
// One thread per edge; float4 gathers of AS/AD, one vector red per edge.
__global__ void edge_den4(const int* __restrict__ src, const int* __restrict__ dst,
                          const float* __restrict__ AS, const float* __restrict__ AD,
                          float* __restrict__ DEN) {
    int e = blockIdx.x * blockDim.x + threadIdx.x;
    if (e >= EE) return;
    int s = __ldg(&src[e]), d = __ldg(&dst[e]);
    float4 a = *(const float4*)&AS[s * 4];
    float4 b = *(const float4*)&AD[d * 4];
    red_add4(&DEN[d * 4],
             __expf(leaky(a.x + b.x)), __expf(leaky(a.y + b.y)),
             __expf(leaky(a.z + b.z)), __expf(leaky(a.w + b.w)));
}

// Hn=1 variant.
__global__ void edge_den1(const int* __restrict__ src, const int* __restrict__ dst,
                          const float* __restrict__ AS, const float* __restrict__ AD,
                          float* __restrict__ DEN) {
    int e = blockIdx.x * blockDim.x + threadIdx.x;
    if (e >= EE) return;
    int s = __ldg(&src[e]), d = __ldg(&dst[e]);
    red_add1(&DEN[d], __expf(leaky(__ldg(&AS[s]) + __ldg(&AD[d]))));
}

// ---------------- edge pass 2: OUT[dst] += ex * h[src] (unnormalized; /DEN later) --------
// 8 floats per lane; lanes-per-edge = HCl/8 (32 for HCl=256, 8 for HCl=64).
// Leader lane of each 8-lane head-group computes ex, shfl-broadcasts it.
__global__ void edge_agg(const float* __restrict__ H, const float* __restrict__ AS,
                         const float* __restrict__ AD, const int* __restrict__ src,
                         const int* __restrict__ dst, float* __restrict__ OUT,
                         int Hn, int lshift) {
    int HCl = Hn * HID;
    long long gid = (long long)blockIdx.x * blockDim.x + threadIdx.x;
    if (gid >= ((long long)EE << lshift)) return;
    int e = (int)(gid >> lshift);
    int li = (int)(gid & ((1 << lshift) - 1));
    int c8 = li << 3;                 // starting column (8 floats per lane)
    int h = c8 >> 6;                  // head for this group
    int s = __ldg(&src[e]), d = __ldg(&dst[e]);
    int lane = threadIdx.x & 31;
    float ex = 0.f;
    if ((lane & 7) == 0) {
        float v = __ldg(&AS[s * Hn + h]) + __ldg(&AD[d * Hn + h]);
        ex = __expf(leaky(v));
    }
    ex = __shfl_sync(0xffffffffu, ex, lane & ~7);
    const float* hp = &H[(size_t)s * HCl + c8];
    float4 v0 = *(const float4*)(hp);
    float4 v1 = *(const float4*)(hp + 4);
    float* op = &OUT[(size_t)d * HCl + c8];
    red_add4(op,     v0.x * ex, v0.y * ex, v0.z * ex, v0.w * ex);
    red_add4(op + 4, v1.x * ex, v1.y * ex, v1.z * ex, v1.w * ex);
}

// DEN[i] -> 1/DEN[i] (0 if no in-edges, matching segment_sum semantics: out stays 0)
__global__ void den_invert(float* __restrict__ DEN, int total) {
    int i = blockIdx.x * blockDim.x + threadIdx.x;
    if (i >= total) return;
    float d = DEN[i];
    DEN[i] = d > 0.f ? 1.0f / d : 0.0f;
}

// ---------------- relu(x*rden + b) in place + BN partial stats ----------------
__global__ void relu_bias_stats(float* __restrict__ X, const float* __restrict__ RDEN,
                                const float* __restrict__ b,
                                float* __restrict__ sum, float* __restrict__ sq,
                                int C, int Hn) {
    int c = threadIdx.x;  // blockDim.x == C
    int h = c >> 6;
    float bb = b[c];
    float s = 0.f, s2 = 0.f;
    for (int r = blockIdx.x; r < NN; r += gridDim.x) {
        float rd = __ldg(&RDEN[r * Hn + h]);
        float v = X[(size_t)r * C + c] * rd + bb;
        v = fmaxf(v, 0.f);
        X[(size_t)r * C + c] = v;
        s += v; s2 += v * v;
    }
    atomicAdd(&sum[c], s);
    atomicAdd(&sq[c], s2);
}

__global__ void bn_finalize(const float* __restrict__ sum, const float* __restrict__ sq,
                            const float* __restrict__ g, const float* __restrict__ be,
                            float* __restrict__ sc, float* __restrict__ sh) {
    int c = threadIdx.x;
    float m = sum[c] / (float)NN;
    float var = sq[c] / (float)NN - m * m;
    float s = rsqrtf(var + EPSV) * g[c];
    sc[c] = s;
    sh[c] = be[c] - m * s;
}

// ---------------- global mean pool (over pre-BN layer-3 output; BN applied in FC) --------
__global__ void pool_kernel(const float* __restrict__ H, const int* __restrict__ batch,
                            float* __restrict__ pool, float* __restrict__ cnt) {
    int idx = blockIdx.x * blockDim.x + threadIdx.x;
    if (idx >= NN * 16) return;
    int n = idx >> 4, l = idx & 15;
    int g = __ldg(&batch[n]);
    float4 v = *(const float4*)&H[(size_t)n * HID + (l << 2)];
    red_add4(&pool[g * HID + (l << 2)], v.x, v.y, v.z, v.w);
    if (l == 0) atomicAdd(&cnt[g], 1.0f);
}

__global__ void final_fc(const float* __restrict__ pool, const float* __restrict__ cnt,
                         const float* __restrict__ sc, const float* __restrict__ sh,
                         const float* __restrict__ fcW, const float* __restrict__ fcb,
                         float* __restrict__ out) {
    int tid = threadIdx.x;
    if (tid >= NGR * NCLS) return;
    int g = tid / NCLS, k = tid - g * NCLS;
    float rc = 1.0f / fmaxf(cnt[g], 1.0f);
    float s = 0.f;
#pragma unroll
    for (int c = 0; c < HID; c++) {
        float feat = pool[g * HID + c] * rc * sc[c] + sh[c];   // BN3 applied post-pool
        s += feat * fcW[c * NCLS + k];
    }
    out[tid] = s + fcb[k];
}

// ---------------- host orchestration ----------------
static inline int cdiv(long long a, int b) { return (int)((a + b - 1) / b); }

struct Scratch {
    float *H, *O, *AS, *AD, *DEN, *SUM, *SQ, *SC, *SH, *PL, *CT;
};

// runs one GAT layer; input X gets optional per-channel affine (prev BN) inside the GEMM.
static void run_layer(const float* X, int K, int Hn, const float* W,
                      const float* asv, const float* adv, const float* b,
                      const float* g, const float* be,
                      const float* scPrev, const float* shPrev,
                      const int* src, const int* dst, const Scratch& S) {
    int HCl = Hn * HID;
    dim3 grid(HCl / 64, cdiv(NN, 128));
    sgemm128x64<<<grid, 256>>>(X, W, S.H, NN, HCl, K, scPrev, shPrev);

    int nw = NN * Hn;
    attn_logits<<<cdiv((long long)nw * 32, 256), 256>>>(S.H, asv, adv, S.AS, S.AD, Hn);

    cudaMemsetAsync(S.DEN, 0, (size_t)NN * Hn * sizeof(float));
    cudaMemsetAsync(S.O, 0, (size_t)NN * HCl * sizeof(float));

    if (Hn == 4)
        edge_den4<<<cdiv(EE, 256), 256>>>(src, dst, S.AS, S.AD, S.DEN);
    else
        edge_den1<<<cdiv(EE, 256), 256>>>(src, dst, S.AS, S.AD, S.DEN);

    int lshift = (HCl == 256) ? 5 : 3;
    edge_agg<<<cdiv((long long)EE << lshift, 256), 256>>>(S.H, S.AS, S.AD, src, dst, S.O,
                                                          Hn, lshift);
    den_invert<<<cdiv(NN * Hn, 256), 256>>>(S.DEN, NN * Hn);

    cudaMemsetAsync(S.SUM, 0, HCl * sizeof(float));
    cudaMemsetAsync(S.SQ, 0, HCl * sizeof(float));
    relu_bias_stats<<<512, HCl>>>(S.O, S.DEN, b, S.SUM, S.SQ, HCl, Hn);
    bn_finalize<<<1, HCl>>>(S.SUM, S.SQ, g, be, S.SC, S.SH);
    // NOTE: BN is NOT applied here; next consumer folds (SC,SH) in.
}

extern "C" void kernel_launch(void* const* d_in, const int* in_sizes, int n_in,
                              void* d_out, int out_size) {
    const float* x      = (const float*)d_in[0];
    const int*   ei     = (const int*)d_in[1];
    const int*   batch  = (const int*)d_in[2];
    const float* W1     = (const float*)d_in[3];
    const float* a_src1 = (const float*)d_in[4];
    const float* a_dst1 = (const float*)d_in[5];
    const float* b1     = (const float*)d_in[6];
    const float* g1     = (const float*)d_in[7];
    const float* be1    = (const float*)d_in[8];
    const float* W2     = (const float*)d_in[9];
    const float* a_src2 = (const float*)d_in[10];
    const float* a_dst2 = (const float*)d_in[11];
    const float* b2     = (const float*)d_in[12];
    const float* g2     = (const float*)d_in[13];
    const float* be2    = (const float*)d_in[14];
    const float* W3     = (const float*)d_in[15];
    const float* a_src3 = (const float*)d_in[16];
    const float* a_dst3 = (const float*)d_in[17];
    const float* b3     = (const float*)d_in[18];
    const float* g3     = (const float*)d_in[19];
    const float* be3    = (const float*)d_in[20];
    const float* fcW    = (const float*)d_in[21];
    const float* fcb    = (const float*)d_in[22];
    const int* src = ei;
    const int* dst = ei + EE;

    Scratch S;
    cudaGetSymbolAddress((void**)&S.H,  g_H);
    cudaGetSymbolAddress((void**)&S.O,  g_O);
    cudaGetSymbolAddress((void**)&S.AS, g_AS);
    cudaGetSymbolAddress((void**)&S.AD, g_AD);
    cudaGetSymbolAddress((void**)&S.DEN, g_DEN);
    cudaGetSymbolAddress((void**)&S.SUM, g_SUM);
    cudaGetSymbolAddress((void**)&S.SQ, g_SQ);
    cudaGetSymbolAddress((void**)&S.SC, g_SC);
    cudaGetSymbolAddress((void**)&S.SH, g_SH);
    cudaGetSymbolAddress((void**)&S.PL, g_PL);
    cudaGetSymbolAddress((void**)&S.CT, g_CT);

    // Layer 1: in=128 -> 4x64 concat (256); raw input, no affine
    run_layer(x,   INC,   NHEADS, W1, a_src1, a_dst1, b1, g1, be1,
              nullptr, nullptr, src, dst, S);
    // Layer 2: 256 -> 4x64 concat; BN1 folded into GEMM A-load
    run_layer(S.O, HCMAX, NHEADS, W2, a_src2, a_dst2, b2, g2, be2,
              S.SC, S.SH, src, dst, S);
    // Layer 3: 256 -> 1x64 (1-head mean == identity); BN2 folded in
    run_layer(S.O, HCMAX, 1,      W3, a_src3, a_dst3, b3, g3, be3,
              S.SC, S.SH, src, dst, S);

    // Global mean pool (pre-BN3) + classifier with BN3 folded in
    cudaMemsetAsync(S.PL, 0, NGR * HID * sizeof(float));
    cudaMemsetAsync(S.CT, 0, NGR * sizeof(float));
    pool_kernel<<<cdiv((long long)NN * 16, 256), 256>>>(S.O, batch, S.PL, S.CT);
    final_fc<<<1, NGR * NCLS>>>(S.PL, S.CT, S.SC, S.SH, fcW, fcb, (float*)d_out);
}